// round 1
// baseline (speedup 1.0000x reference)
#include <cuda_runtime.h>
#include <cuda_bf16.h>
#include <cstdint>

#define NUM_PROTEINS 19000
#define NUM_DRUGS    1024
#define IN_CH        256
#define EMBED        256
#define E_SG         1500000
#define N_SG         800000
#define B_DD         4096

// ---------------- scratch (device globals; no allocation) ----------------
__device__ float g_hw [NUM_PROTEINS * EMBED];   // current layer's h@W
__device__ float g_h1 [NUM_PROTEINS * EMBED];   // relu(gcn1)
__device__ float g_h2 [NUM_PROTEINS * EMBED];   // gcn2 + h1
__device__ int   g_degi[NUM_PROTEINS];
__device__ float g_dinv[NUM_PROTEINS];
__device__ int   g_rowstart[NUM_PROTEINS + 1];
__device__ int   g_cursor[NUM_PROTEINS];
__device__ int   g_esrc[E_SG];
__device__ float g_ew  [E_SG];
__device__ float g_dsum[NUM_DRUGS * EMBED];
__device__ int   g_dcnt[NUM_DRUGS];

// ---------------- zero scratch ----------------
__global__ void k_zero() {
    int i = blockIdx.x * blockDim.x + threadIdx.x;
    if (i < NUM_DRUGS * EMBED) g_dsum[i] = 0.f;
    if (i < NUM_PROTEINS)      g_degi[i] = 0;
    if (i < NUM_DRUGS)         g_dcnt[i] = 0;
}

// ---------------- degree count ----------------
__global__ void k_count(const int* __restrict__ ei) {
    int e = blockIdx.x * blockDim.x + threadIdx.x;
    if (e >= E_SG) return;
    atomicAdd(&g_degi[ei[E_SG + e]], 1);
}

// ---------------- dinv ----------------
__global__ void k_dinv() {
    int i = blockIdx.x * blockDim.x + threadIdx.x;
    if (i >= NUM_PROTEINS) return;
    g_dinv[i] = rsqrtf((float)g_degi[i] + 1.0f);
}

// ---------------- single-block prefix scan over 19000 degrees ----------------
__global__ void k_scan() {
    __shared__ int sm[1024];
    const int CH = 19;                       // 1024*19 = 19456 >= 19000
    int t = threadIdx.x;
    int base = t * CH;
    int s = 0;
#pragma unroll
    for (int i = 0; i < CH; ++i) {
        int j = base + i;
        if (j < NUM_PROTEINS) s += g_degi[j];
    }
    sm[t] = s;
    __syncthreads();
    for (int off = 1; off < 1024; off <<= 1) {
        int v = (t >= off) ? sm[t - off] : 0;
        __syncthreads();
        sm[t] += v;
        __syncthreads();
    }
    int run = (t == 0) ? 0 : sm[t - 1];
    for (int i = 0; i < CH; ++i) {
        int j = base + i;
        if (j < NUM_PROTEINS) {
            g_rowstart[j] = run;
            g_cursor[j]   = run;
            run += g_degi[j];
        }
    }
    if (t == 0) g_rowstart[NUM_PROTEINS] = E_SG;
}

// ---------------- CSR fill (bucket edges by dst, precompute edge weight) ----------------
__global__ void k_fill(const int* __restrict__ ei) {
    int e = blockIdx.x * blockDim.x + threadIdx.x;
    if (e >= E_SG) return;
    int s = ei[e];
    int d = ei[E_SG + e];
    int pos = atomicAdd(&g_cursor[d], 1);
    g_esrc[pos] = s;
    g_ew[pos]   = g_dinv[s] * g_dinv[d];
}

// ---------------- fp32 tiled GEMM: C[M,256] = A[M,256] @ B[256,256] ----------------
#define GBM 128
#define GBN 64
#define GBK 32
__global__ void k_gemm(const float* __restrict__ A, const float* __restrict__ B,
                       float* __restrict__ C, int M) {
    __shared__ float As[GBK][GBM + 1];
    __shared__ float Bs[GBK][GBN];
    int bm = blockIdx.x * GBM;
    int bn = blockIdx.y * GBN;
    int tid = threadIdx.x;
    int tr = tid >> 4;          // 0..15
    int tc = tid & 15;          // 0..15
    float acc[8][4];
#pragma unroll
    for (int i = 0; i < 8; ++i)
#pragma unroll
        for (int j = 0; j < 4; ++j) acc[i][j] = 0.f;

    for (int k0 = 0; k0 < 256; k0 += GBK) {
        // A tile: 128 x 32 -> transposed into smem
#pragma unroll
        for (int l = 0; l < 4; ++l) {
            int idx = tid + l * 256;
            int r  = idx >> 3;
            int c4 = (idx & 7) * 4;
            float4 v = make_float4(0.f, 0.f, 0.f, 0.f);
            int gr = bm + r;
            if (gr < M) v = *(const float4*)(A + (size_t)gr * 256 + k0 + c4);
            As[c4    ][r] = v.x;
            As[c4 + 1][r] = v.y;
            As[c4 + 2][r] = v.z;
            As[c4 + 3][r] = v.w;
        }
        // B tile: 32 x 64
#pragma unroll
        for (int l = 0; l < 2; ++l) {
            int idx = tid + l * 256;
            int r  = idx >> 4;
            int c4 = (idx & 15) * 4;
            float4 v = *(const float4*)(B + (size_t)(k0 + r) * 256 + bn + c4);
            *(float4*)&Bs[r][c4] = v;
        }
        __syncthreads();
#pragma unroll
        for (int k = 0; k < GBK; ++k) {
            float a[8], b[4];
#pragma unroll
            for (int i = 0; i < 8; ++i) a[i] = As[k][tr * 8 + i];
#pragma unroll
            for (int j = 0; j < 4; ++j) b[j] = Bs[k][tc * 4 + j];
#pragma unroll
            for (int i = 0; i < 8; ++i)
#pragma unroll
                for (int j = 0; j < 4; ++j) acc[i][j] = fmaf(a[i], b[j], acc[i][j]);
        }
        __syncthreads();
    }
#pragma unroll
    for (int i = 0; i < 8; ++i) {
        int gr = bm + tr * 8 + i;
        if (gr < M) {
            float4 v = make_float4(acc[i][0], acc[i][1], acc[i][2], acc[i][3]);
            *(float4*)(C + (size_t)gr * 256 + bn + tc * 4) = v;
        }
    }
}

// ---------------- warp-per-row CSR aggregation + fused epilogue ----------------
// out[row] = sum_{e in row} w_e * hw[src_e]  +  hw[row]*dinv[row]^2 + bias
//            (+ resid[row] if resid != null)   (relu if do_relu)
__global__ void k_agg(const float* __restrict__ hw, const float* __restrict__ bias,
                      const float* __restrict__ resid, float* __restrict__ outp,
                      int do_relu) {
    int warp = (blockIdx.x * blockDim.x + threadIdx.x) >> 5;
    if (warp >= NUM_PROTEINS) return;
    int lane = threadIdx.x & 31;

    float4 a0 = make_float4(0.f, 0.f, 0.f, 0.f);
    float4 a1 = make_float4(0.f, 0.f, 0.f, 0.f);
    int beg = g_rowstart[warp];
    int end = g_rowstart[warp + 1];

    for (int base = beg; base < end; base += 32) {
        int idx = base + lane;
        int   sreg = 0;
        float wreg = 0.f;
        if (idx < end) { sreg = g_esrc[idx]; wreg = g_ew[idx]; }
        int n = end - base; if (n > 32) n = 32;
        for (int j = 0; j < n; ++j) {
            int   sj = __shfl_sync(0xffffffffu, sreg, j);
            float wj = __shfl_sync(0xffffffffu, wreg, j);
            const float4* p = (const float4*)(hw + (size_t)sj * EMBED + lane * 8);
            float4 v0 = p[0];
            float4 v1 = p[1];
            a0.x = fmaf(wj, v0.x, a0.x);
            a0.y = fmaf(wj, v0.y, a0.y);
            a0.z = fmaf(wj, v0.z, a0.z);
            a0.w = fmaf(wj, v0.w, a0.w);
            a1.x = fmaf(wj, v1.x, a1.x);
            a1.y = fmaf(wj, v1.y, a1.y);
            a1.z = fmaf(wj, v1.z, a1.z);
            a1.w = fmaf(wj, v1.w, a1.w);
        }
    }

    float selfn = g_dinv[warp] * g_dinv[warp];
    const float4* ph = (const float4*)(hw + (size_t)warp * EMBED + lane * 8);
    float4 h0 = ph[0], h1v = ph[1];
    const float4* pb = (const float4*)(bias + lane * 8);
    float4 b0 = pb[0], b1v = pb[1];
    a0.x += h0.x * selfn + b0.x;   a0.y += h0.y * selfn + b0.y;
    a0.z += h0.z * selfn + b0.z;   a0.w += h0.w * selfn + b0.w;
    a1.x += h1v.x * selfn + b1v.x; a1.y += h1v.y * selfn + b1v.y;
    a1.z += h1v.z * selfn + b1v.z; a1.w += h1v.w * selfn + b1v.w;

    if (resid) {
        const float4* pr = (const float4*)(resid + (size_t)warp * EMBED + lane * 8);
        float4 r0 = pr[0], r1 = pr[1];
        a0.x += r0.x; a0.y += r0.y; a0.z += r0.z; a0.w += r0.w;
        a1.x += r1.x; a1.y += r1.y; a1.z += r1.z; a1.w += r1.w;
    }
    if (do_relu) {
        a0.x = fmaxf(a0.x, 0.f); a0.y = fmaxf(a0.y, 0.f);
        a0.z = fmaxf(a0.z, 0.f); a0.w = fmaxf(a0.w, 0.f);
        a1.x = fmaxf(a1.x, 0.f); a1.y = fmaxf(a1.y, 0.f);
        a1.z = fmaxf(a1.z, 0.f); a1.w = fmaxf(a1.w, 0.f);
    }
    float4* po = (float4*)(outp + (size_t)warp * EMBED + lane * 8);
    po[0] = a0;
    po[1] = a1;
}

// ---------------- segmented-sorted pooling: 800K nodes -> 1024 drug sums ----------------
#define NPB 1024
__global__ void k_pool(const int* __restrict__ nodes, const int* __restrict__ didx) {
    __shared__ int sn[NPB];
    __shared__ int sd[NPB];
    int n0  = blockIdx.x * NPB;
    int cnt = N_SG - n0; if (cnt > NPB) cnt = NPB;
    for (int i = threadIdx.x; i < cnt; i += blockDim.x) {
        sn[i] = nodes[n0 + i];
        sd[i] = didx[n0 + i];
    }
    __syncthreads();
    int c = threadIdx.x;            // channel 0..255
    float acc = 0.f;
    int cur = sd[0];
    int ccount = 0;
    for (int i = 0; i < cnt; ++i) {
        int d = sd[i];
        if (d != cur) {
            atomicAdd(&g_dsum[(size_t)cur * EMBED + c], acc);
            if (c == 0) atomicAdd(&g_dcnt[cur], ccount);
            acc = 0.f; ccount = 0; cur = d;
        }
        acc += g_h2[(size_t)sn[i] * EMBED + c];
        ccount++;
    }
    atomicAdd(&g_dsum[(size_t)cur * EMBED + c], acc);
    if (c == 0) atomicAdd(&g_dcnt[cur], ccount);
}

// ---------------- head: warp-per-pair dot products ----------------
__global__ void k_head(const int* __restrict__ ddb, float* __restrict__ out) {
    int warp = (blockIdx.x * blockDim.x + threadIdx.x) >> 5;
    if (warp >= B_DD) return;
    int lane = threadIdx.x & 31;
    int a = ddb[warp];
    int b = ddb[B_DD + warp];
    const float4* pa = (const float4*)(g_dsum + (size_t)a * EMBED + lane * 8);
    const float4* pb = (const float4*)(g_dsum + (size_t)b * EMBED + lane * 8);
    float4 a0 = pa[0], a1 = pa[1];
    float4 b0 = pb[0], b1 = pb[1];
    float dot = a0.x * b0.x + a0.y * b0.y + a0.z * b0.z + a0.w * b0.w
              + a1.x * b1.x + a1.y * b1.y + a1.z * b1.z + a1.w * b1.w;
#pragma unroll
    for (int off = 16; off > 0; off >>= 1)
        dot += __shfl_down_sync(0xffffffffu, dot, off);
    if (lane == 0) {
        float ca = (float)max(g_dcnt[a], 1);
        float cb = (float)max(g_dcnt[b], 1);
        out[warp] = dot / (ca * cb);
    }
}

// ---------------- launch ----------------
extern "C" void kernel_launch(void* const* d_in, const int* in_sizes, int n_in,
                              void* d_out, int out_size) {
    const float* x   = (const float*)d_in[0];   // [19000,256]
    const int*   ddb = (const int*)  d_in[1];   // [2,4096]
    // d_in[2] edge_attr, d_in[3] edge_cell_lines: unused by reference
    const int*   ei  = (const int*)  d_in[4];   // [2,1500000]
    const int*   sgn = (const int*)  d_in[5];   // [800000]
    const int*   sga = (const int*)  d_in[6];   // [800000] sorted drug ids
    const float* W1  = (const float*)d_in[7];
    const float* b1  = (const float*)d_in[8];
    const float* W2  = (const float*)d_in[9];
    const float* b2  = (const float*)d_in[10];
    float* out = (float*)d_out;

    float *hw, *h1, *h2;
    cudaGetSymbolAddress((void**)&hw, g_hw);
    cudaGetSymbolAddress((void**)&h1, g_h1);
    cudaGetSymbolAddress((void**)&h2, g_h2);

    k_zero<<<(NUM_DRUGS * EMBED + 255) / 256, 256>>>();
    k_count<<<(E_SG + 255) / 256, 256>>>(ei);
    k_dinv<<<(NUM_PROTEINS + 255) / 256, 256>>>();
    k_scan<<<1, 1024>>>();
    k_fill<<<(E_SG + 255) / 256, 256>>>(ei);

    dim3 ggrid((NUM_PROTEINS + GBM - 1) / GBM, 256 / GBN);
    // Layer 1
    k_gemm<<<ggrid, 256>>>(x, W1, hw, NUM_PROTEINS);
    k_agg<<<(NUM_PROTEINS * 32 + 255) / 256, 256>>>(hw, b1, nullptr, h1, 1);
    // Layer 2 (residual, no relu)
    k_gemm<<<ggrid, 256>>>(h1, W2, hw, NUM_PROTEINS);
    k_agg<<<(NUM_PROTEINS * 32 + 255) / 256, 256>>>(hw, b2, h1, h2, 0);

    k_pool<<<(N_SG + NPB - 1) / NPB, 256>>>(sgn, sga);
    k_head<<<(B_DD * 32 + 255) / 256, 256>>>(ddb, out);
}

// round 2
// speedup vs baseline: 1.5180x; 1.5180x over previous
#include <cuda_runtime.h>
#include <cuda_fp16.h>
#include <mma.h>
#include <cstdint>
using namespace nvcuda;

#define NUM_PROTEINS 19000
#define M_PAD        19072          // 149 * 128
#define NUM_DRUGS    1024
#define EMBED        256
#define E_SG         1500000
#define N_SG         800000
#define B_DD         4096

// ---------------- scratch (device globals; no allocation) ----------------
__device__ float g_hw  [M_PAD * EMBED];                 // GEMM output fp32 (padded)
__device__ uint4 g_hwh4[NUM_PROTEINS * EMBED / 8];      // hw as fp16
__device__ uint4 g_h1h4[NUM_PROTEINS * EMBED / 8];      // h1 as fp16
__device__ uint4 g_h2h4[NUM_PROTEINS * EMBED / 8];      // h2 as fp16
__device__ uint4 g_W1h4[EMBED * EMBED / 8];
__device__ uint4 g_W2h4[EMBED * EMBED / 8];
__device__ int   g_degi[NUM_PROTEINS];
__device__ float g_dinv[NUM_PROTEINS];
__device__ int   g_rowstart[NUM_PROTEINS + 1];
__device__ int   g_cursor[NUM_PROTEINS];
__device__ int   g_esrc[E_SG];
__device__ float g_ew  [E_SG];
__device__ float g_dsum[NUM_DRUGS * EMBED];
__device__ int   g_dcnt[NUM_DRUGS];

// ---------------- zero scratch ----------------
__global__ void k_zero() {
    int i = blockIdx.x * blockDim.x + threadIdx.x;
    if (i < NUM_DRUGS * EMBED) g_dsum[i] = 0.f;
    if (i < NUM_PROTEINS)      g_degi[i] = 0;
    if (i < NUM_DRUGS)         g_dcnt[i] = 0;
}

// ---------------- convert W1/W2 to fp16 ----------------
__global__ void k_convW(const float* __restrict__ W1, const float* __restrict__ W2,
                        __half* __restrict__ W1h, __half* __restrict__ W2h) {
    int i = blockIdx.x * blockDim.x + threadIdx.x;
    const int n4 = EMBED * EMBED / 4;   // 16384
    if (i < n4) {
        float4 v = ((const float4*)W1)[i];
        ((__half2*)W1h)[2 * i]     = __floats2half2_rn(v.x, v.y);
        ((__half2*)W1h)[2 * i + 1] = __floats2half2_rn(v.z, v.w);
    } else if (i < 2 * n4) {
        int j = i - n4;
        float4 v = ((const float4*)W2)[j];
        ((__half2*)W2h)[2 * j]     = __floats2half2_rn(v.x, v.y);
        ((__half2*)W2h)[2 * j + 1] = __floats2half2_rn(v.z, v.w);
    }
}

// ---------------- degree count ----------------
__global__ void k_count(const int* __restrict__ ei) {
    int e = blockIdx.x * blockDim.x + threadIdx.x;
    if (e >= E_SG) return;
    atomicAdd(&g_degi[ei[E_SG + e]], 1);
}

// ---------------- fused prefix scan + dinv (single block, 256 threads) ----------------
__global__ void k_scan() {
    __shared__ int warpsum[8];
    int t = threadIdx.x;
    const int CH = 76;                  // 250 threads * 76 = 19000 exactly
    int base = t * CH;
    int s = 0;
    if (t < 250) {
        const int4* p = (const int4*)(g_degi + base);
#pragma unroll
        for (int i = 0; i < 19; ++i) { int4 v = p[i]; s += v.x + v.y + v.z + v.w; }
    }
    int lane = t & 31, w = t >> 5;
    int v = s;
#pragma unroll
    for (int off = 1; off < 32; off <<= 1) {
        int u = __shfl_up_sync(0xffffffffu, v, off);
        if (lane >= off) v += u;
    }
    if (lane == 31) warpsum[w] = v;
    __syncthreads();
    if (w == 0) {
        int ws = (lane < 8) ? warpsum[lane] : 0;
#pragma unroll
        for (int off = 1; off < 8; off <<= 1) {
            int u = __shfl_up_sync(0xffffffffu, ws, off);
            if (lane >= off) ws += u;
        }
        if (lane < 8) warpsum[lane] = ws;
    }
    __syncthreads();
    int run = v - s + (w ? warpsum[w - 1] : 0);   // exclusive prefix
    if (t < 250) {
#pragma unroll 4
        for (int i = 0; i < CH; ++i) {
            int j = base + i;
            int d = g_degi[j];
            g_rowstart[j] = run;
            g_cursor[j]   = run;
            g_dinv[j]     = rsqrtf((float)d + 1.0f);
            run += d;
        }
    }
    if (t == 255) g_rowstart[NUM_PROTEINS] = E_SG;
}

// ---------------- CSR fill ----------------
__global__ void k_fill(const int* __restrict__ ei) {
    int e = blockIdx.x * blockDim.x + threadIdx.x;
    if (e >= E_SG) return;
    int s = ei[e];
    int d = ei[E_SG + e];
    int pos = atomicAdd(&g_cursor[d], 1);
    g_esrc[pos] = s;
    g_ew[pos]   = g_dinv[s] * g_dinv[d];
}

// ---------------- WMMA fp16 GEMM: C[M,256] = A[M,256] @ B[256,256], fp32 out ----------------
// AHALF=0: A is fp32 (converted on the fly). AHALF=1: A is fp16.
template<int AHALF>
__global__ void k_gemm_w(const void* __restrict__ Ap, const __half* __restrict__ B,
                         float* __restrict__ C, int M) {
    __shared__ __align__(16) __half As[128][40];
    __shared__ __align__(16) __half Bs[32][72];
    int bm = blockIdx.x * 128, bn = blockIdx.y * 64;
    int tid = threadIdx.x;
    int warp = tid >> 5;
    int wm = warp & 3, wn = warp >> 2;
    wmma::fragment<wmma::accumulator, 16, 16, 16, float> c[2][2];
#pragma unroll
    for (int i = 0; i < 2; ++i)
#pragma unroll
        for (int j = 0; j < 2; ++j) wmma::fill_fragment(c[i][j], 0.f);

    for (int k0 = 0; k0 < 256; k0 += 32) {
        if (AHALF) {
            const __half* A = (const __half*)Ap;
#pragma unroll
            for (int l = 0; l < 2; ++l) {
                int idx = tid + l * 256;
                int r = idx >> 2, seg = (idx & 3) * 8;
                uint4 v = make_uint4(0, 0, 0, 0);
                int gr = bm + r;
                if (gr < M) v = *(const uint4*)(A + (size_t)gr * 256 + k0 + seg);
                *(uint4*)&As[r][seg] = v;
            }
        } else {
            const float* A = (const float*)Ap;
#pragma unroll
            for (int l = 0; l < 4; ++l) {
                int idx = tid + l * 256;
                int r = idx >> 3, c4 = (idx & 7) * 4;
                float4 v = make_float4(0.f, 0.f, 0.f, 0.f);
                int gr = bm + r;
                if (gr < M) v = *(const float4*)(A + (size_t)gr * 256 + k0 + c4);
                *(__half2*)&As[r][c4]     = __floats2half2_rn(v.x, v.y);
                *(__half2*)&As[r][c4 + 2] = __floats2half2_rn(v.z, v.w);
            }
        }
        {
            int r = tid >> 3, seg = (tid & 7) * 8;
            uint4 v = *(const uint4*)(B + (size_t)(k0 + r) * 256 + bn + seg);
            *(uint4*)&Bs[r][seg] = v;
        }
        __syncthreads();
#pragma unroll
        for (int kk = 0; kk < 32; kk += 16) {
            wmma::fragment<wmma::matrix_a, 16, 16, 16, __half, wmma::row_major> a0, a1;
            wmma::fragment<wmma::matrix_b, 16, 16, 16, __half, wmma::row_major> b0, b1;
            wmma::load_matrix_sync(a0, &As[wm * 32][kk], 40);
            wmma::load_matrix_sync(a1, &As[wm * 32 + 16][kk], 40);
            wmma::load_matrix_sync(b0, &Bs[kk][wn * 32], 72);
            wmma::load_matrix_sync(b1, &Bs[kk][wn * 32 + 16], 72);
            wmma::mma_sync(c[0][0], a0, b0, c[0][0]);
            wmma::mma_sync(c[0][1], a0, b1, c[0][1]);
            wmma::mma_sync(c[1][0], a1, b0, c[1][0]);
            wmma::mma_sync(c[1][1], a1, b1, c[1][1]);
        }
        __syncthreads();
    }
#pragma unroll
    for (int i = 0; i < 2; ++i)
#pragma unroll
        for (int j = 0; j < 2; ++j)
            wmma::store_matrix_sync(&C[(size_t)(bm + wm * 32 + i * 16) * 256 + bn + wn * 32 + j * 16],
                                    c[i][j], 256, wmma::mem_row_major);
}

// ---------------- fp32 -> fp16 convert (hw) ----------------
__global__ void k_f2h(const float* __restrict__ src, __half* __restrict__ dst) {
    int i = blockIdx.x * blockDim.x + threadIdx.x;
    if (i >= NUM_PROTEINS * EMBED / 4) return;
    float4 v = ((const float4*)src)[i];
    ((__half2*)dst)[2 * i]     = __floats2half2_rn(v.x, v.y);
    ((__half2*)dst)[2 * i + 1] = __floats2half2_rn(v.z, v.w);
}

// ---------------- warp-per-row CSR aggregation, fp16 gather, fp32 accum ----------------
__global__ void k_agg(const __half* __restrict__ hw, const float* __restrict__ bias,
                      const __half* __restrict__ resid, __half* __restrict__ outp,
                      int do_relu) {
    int warp = (blockIdx.x * blockDim.x + threadIdx.x) >> 5;
    if (warp >= NUM_PROTEINS) return;
    int lane = threadIdx.x & 31;
    float acc[8];
#pragma unroll
    for (int i = 0; i < 8; ++i) acc[i] = 0.f;
    int beg = g_rowstart[warp], end = g_rowstart[warp + 1];

    for (int base = beg; base < end; base += 32) {
        int idx = base + lane;
        int   sreg = 0;
        float wreg = 0.f;
        if (idx < end) { sreg = g_esrc[idx]; wreg = g_ew[idx]; }
        int n = end - base; if (n > 32) n = 32;
        for (int j = 0; j < n; ++j) {
            int   sj = __shfl_sync(0xffffffffu, sreg, j);
            float wj = __shfl_sync(0xffffffffu, wreg, j);
            uint4 vv = *(const uint4*)(hw + (size_t)sj * EMBED + lane * 8);
            __half2* h = (__half2*)&vv;
#pragma unroll
            for (int q = 0; q < 4; ++q) {
                float2 f = __half22float2(h[q]);
                acc[2 * q]     = fmaf(wj, f.x, acc[2 * q]);
                acc[2 * q + 1] = fmaf(wj, f.y, acc[2 * q + 1]);
            }
        }
    }

    float selfn = g_dinv[warp] * g_dinv[warp];
    uint4 sv = *(const uint4*)(hw + (size_t)warp * EMBED + lane * 8);
    __half2* sh = (__half2*)&sv;
    float4 b0 = *(const float4*)(bias + lane * 8);
    float4 b1 = *(const float4*)(bias + lane * 8 + 4);
    float bb[8] = {b0.x, b0.y, b0.z, b0.w, b1.x, b1.y, b1.z, b1.w};
#pragma unroll
    for (int q = 0; q < 4; ++q) {
        float2 f = __half22float2(sh[q]);
        acc[2 * q]     += selfn * f.x + bb[2 * q];
        acc[2 * q + 1] += selfn * f.y + bb[2 * q + 1];
    }
    if (resid) {
        uint4 rv = *(const uint4*)(resid + (size_t)warp * EMBED + lane * 8);
        __half2* rh = (__half2*)&rv;
#pragma unroll
        for (int q = 0; q < 4; ++q) {
            float2 f = __half22float2(rh[q]);
            acc[2 * q] += f.x; acc[2 * q + 1] += f.y;
        }
    }
    if (do_relu) {
#pragma unroll
        for (int i = 0; i < 8; ++i) acc[i] = fmaxf(acc[i], 0.f);
    }
    uint4 ov; __half2* oh = (__half2*)&ov;
#pragma unroll
    for (int q = 0; q < 4; ++q) oh[q] = __floats2half2_rn(acc[2 * q], acc[2 * q + 1]);
    *(uint4*)(outp + (size_t)warp * EMBED + lane * 8) = ov;
}

// ---------------- segmented-sorted pooling ----------------
#define NPB 1024
__global__ void k_pool(const int* __restrict__ nodes, const int* __restrict__ didx,
                       const __half* __restrict__ h2) {
    __shared__ int sn[NPB];
    __shared__ int sd[NPB];
    int n0  = blockIdx.x * NPB;
    int cnt = N_SG - n0; if (cnt > NPB) cnt = NPB;
    for (int i = threadIdx.x; i < cnt; i += blockDim.x) {
        sn[i] = nodes[n0 + i];
        sd[i] = didx[n0 + i];
    }
    __syncthreads();
    int c = threadIdx.x;
    float acc = 0.f;
    int cur = sd[0];
    int cc = 0;
    for (int i = 0; i < cnt; ++i) {
        int d = sd[i];
        if (d != cur) {
            atomicAdd(&g_dsum[(size_t)cur * EMBED + c], acc);
            if (c == 0) atomicAdd(&g_dcnt[cur], cc);
            acc = 0.f; cc = 0; cur = d;
        }
        acc += __half2float(h2[(size_t)sn[i] * EMBED + c]);
        cc++;
    }
    atomicAdd(&g_dsum[(size_t)cur * EMBED + c], acc);
    if (c == 0) atomicAdd(&g_dcnt[cur], cc);
}

// ---------------- head ----------------
__global__ void k_head(const int* __restrict__ ddb, float* __restrict__ out) {
    int warp = (blockIdx.x * blockDim.x + threadIdx.x) >> 5;
    if (warp >= B_DD) return;
    int lane = threadIdx.x & 31;
    int a = ddb[warp];
    int b = ddb[B_DD + warp];
    const float4* pa = (const float4*)(g_dsum + (size_t)a * EMBED + lane * 8);
    const float4* pb = (const float4*)(g_dsum + (size_t)b * EMBED + lane * 8);
    float4 a0 = pa[0], a1 = pa[1];
    float4 b0 = pb[0], b1 = pb[1];
    float dot = a0.x * b0.x + a0.y * b0.y + a0.z * b0.z + a0.w * b0.w
              + a1.x * b1.x + a1.y * b1.y + a1.z * b1.z + a1.w * b1.w;
#pragma unroll
    for (int off = 16; off > 0; off >>= 1)
        dot += __shfl_down_sync(0xffffffffu, dot, off);
    if (lane == 0) {
        float ca = (float)max(g_dcnt[a], 1);
        float cb = (float)max(g_dcnt[b], 1);
        out[warp] = dot / (ca * cb);
    }
}

// ---------------- launch ----------------
extern "C" void kernel_launch(void* const* d_in, const int* in_sizes, int n_in,
                              void* d_out, int out_size) {
    const float* x   = (const float*)d_in[0];
    const int*   ddb = (const int*)  d_in[1];
    const int*   ei  = (const int*)  d_in[4];
    const int*   sgn = (const int*)  d_in[5];
    const int*   sga = (const int*)  d_in[6];
    const float* W1  = (const float*)d_in[7];
    const float* b1  = (const float*)d_in[8];
    const float* W2  = (const float*)d_in[9];
    const float* b2  = (const float*)d_in[10];
    float* out = (float*)d_out;

    float *hw; __half *hwh, *h1h, *h2h, *W1h, *W2h;
    cudaGetSymbolAddress((void**)&hw,  g_hw);
    cudaGetSymbolAddress((void**)&hwh, g_hwh4);
    cudaGetSymbolAddress((void**)&h1h, g_h1h4);
    cudaGetSymbolAddress((void**)&h2h, g_h2h4);
    cudaGetSymbolAddress((void**)&W1h, g_W1h4);
    cudaGetSymbolAddress((void**)&W2h, g_W2h4);

    k_zero<<<(NUM_DRUGS * EMBED + 255) / 256, 256>>>();
    k_convW<<<(2 * EMBED * EMBED / 4 + 255) / 256, 256>>>(W1, W2, W1h, W2h);
    k_count<<<(E_SG + 255) / 256, 256>>>(ei);
    k_scan<<<1, 256>>>();
    k_fill<<<(E_SG + 255) / 256, 256>>>(ei);

    dim3 ggrid(M_PAD / 128, 256 / 64);
    // Layer 1
    k_gemm_w<0><<<ggrid, 256>>>((const void*)x, W1h, hw, NUM_PROTEINS);
    k_f2h<<<(NUM_PROTEINS * EMBED / 4 + 255) / 256, 256>>>(hw, hwh);
    k_agg<<<(NUM_PROTEINS * 32 + 255) / 256, 256>>>(hwh, b1, (const __half*)nullptr, h1h, 1);
    // Layer 2 (residual, no relu)
    k_gemm_w<1><<<ggrid, 256>>>((const void*)h1h, W2h, hw, NUM_PROTEINS);
    k_f2h<<<(NUM_PROTEINS * EMBED / 4 + 255) / 256, 256>>>(hw, hwh);
    k_agg<<<(NUM_PROTEINS * 32 + 255) / 256, 256>>>(hwh, b2, h1h, h2h, 0);

    k_pool<<<(N_SG + NPB - 1) / NPB, 256>>>(sgn, sga, h2h);
    k_head<<<(B_DD * 32 + 255) / 256, 256>>>(ddb, out);
}

// round 3
// speedup vs baseline: 1.6649x; 1.0968x over previous
#include <cuda_runtime.h>
#include <cuda_fp16.h>
#include <mma.h>
#include <cstdint>
using namespace nvcuda;

#define NUM_PROTEINS 19000
#define NUM_DRUGS    1024
#define EMBED        256
#define E_SG         1500000
#define N_SG         800000
#define B_DD         4096
#define NBLK         149            // ceil(19000/128)

// ---------------- scratch (device globals; no allocation) ----------------
__device__ uint4 g_hwh4[NUM_PROTEINS * EMBED / 8];      // hw as fp16
__device__ uint4 g_h1h4[NUM_PROTEINS * EMBED / 8];      // h1 as fp16
__device__ uint4 g_h2h4[NUM_PROTEINS * EMBED / 8];      // h2 as fp16
__device__ uint4 g_W1h4[EMBED * EMBED / 8];
__device__ uint4 g_W2h4[EMBED * EMBED / 8];
__device__ int   g_degi[NUM_PROTEINS];
__device__ float g_dinv[NUM_PROTEINS];
__device__ int   g_rowstart[NUM_PROTEINS + 1];
__device__ int   g_cursor[NUM_PROTEINS];
__device__ int   g_esrc[E_SG];
__device__ int   g_bsum[NBLK];
__device__ int   g_boff[NBLK];
__device__ int   g_dstart[NUM_DRUGS + 1];
__device__ float g_demb[NUM_DRUGS * EMBED];

// ---------------- prep0: convert W1/W2 to fp16, zero degree counters ----------------
__global__ void k_prep0(const float* __restrict__ W1, const float* __restrict__ W2,
                        __half* __restrict__ W1h, __half* __restrict__ W2h) {
    int i = blockIdx.x * blockDim.x + threadIdx.x;   // 0..32767
    const int n4 = EMBED * EMBED / 4;                // 16384 float4s per matrix
    if (i < n4) {
        float4 v = ((const float4*)W1)[i];
        ((__half2*)W1h)[2 * i]     = __floats2half2_rn(v.x, v.y);
        ((__half2*)W1h)[2 * i + 1] = __floats2half2_rn(v.z, v.w);
    } else {
        int j = i - n4;
        float4 v = ((const float4*)W2)[j];
        ((__half2*)W2h)[2 * j]     = __floats2half2_rn(v.x, v.y);
        ((__half2*)W2h)[2 * j + 1] = __floats2half2_rn(v.z, v.w);
    }
    if (i < NUM_PROTEINS) g_degi[i] = 0;
}

// ---------------- degree count ----------------
__global__ void k_count(const int* __restrict__ ei) {
    int e = blockIdx.x * blockDim.x + threadIdx.x;
    if (e >= E_SG) return;
    atomicAdd(&g_degi[ei[E_SG + e]], 1);
}

// ---------------- scan phase 1: per-block degree sums ----------------
__global__ void k_bsum() {
    __shared__ int ws[4];
    int j = blockIdx.x * 128 + threadIdx.x;
    int v = (j < NUM_PROTEINS) ? g_degi[j] : 0;
#pragma unroll
    for (int off = 16; off > 0; off >>= 1) v += __shfl_down_sync(0xffffffffu, v, off);
    int lane = threadIdx.x & 31, w = threadIdx.x >> 5;
    if (lane == 0) ws[w] = v;
    __syncthreads();
    if (threadIdx.x == 0) g_bsum[blockIdx.x] = ws[0] + ws[1] + ws[2] + ws[3];
}

// ---------------- scan phase 2: exclusive scan of 149 block sums ----------------
__global__ void k_bscan() {
    __shared__ int wsum[6];
    int t = threadIdx.x;                 // 192 threads
    int lane = t & 31, w = t >> 5;
    int s = (t < NBLK) ? g_bsum[t] : 0;
    int v = s;
#pragma unroll
    for (int off = 1; off < 32; off <<= 1) {
        int u = __shfl_up_sync(0xffffffffu, v, off);
        if (lane >= off) v += u;
    }
    if (lane == 31) wsum[w] = v;
    __syncthreads();
    if (w == 0 && lane < 6) {
        int x = wsum[lane];
#pragma unroll
        for (int off = 1; off < 6; off <<= 1) {
            int u = __shfl_up_sync(0x3fu, x, off);
            if (lane >= off) x += u;
        }
        wsum[lane] = x;
    }
    __syncthreads();
    int excl = v - s + (w ? wsum[w - 1] : 0);
    if (t < NBLK) g_boff[t] = excl;
}

// ---------------- scan phase 3: write rowstart/cursor/dinv ----------------
__global__ void k_write() {
    __shared__ int wsum[4];
    int t = threadIdx.x;
    int j = blockIdx.x * 128 + t;
    int d = (j < NUM_PROTEINS) ? g_degi[j] : 0;
    int lane = t & 31, w = t >> 5;
    int v = d;
#pragma unroll
    for (int off = 1; off < 32; off <<= 1) {
        int u = __shfl_up_sync(0xffffffffu, v, off);
        if (lane >= off) v += u;
    }
    if (lane == 31) wsum[w] = v;
    __syncthreads();
    if (w == 0 && lane < 4) {
        int x = wsum[lane];
#pragma unroll
        for (int off = 1; off < 4; off <<= 1) {
            int u = __shfl_up_sync(0xfu, x, off);
            if (lane >= off) x += u;
        }
        wsum[lane] = x;
    }
    __syncthreads();
    int run = g_boff[blockIdx.x] + v - d + (w ? wsum[w - 1] : 0);
    if (j < NUM_PROTEINS) {
        g_rowstart[j] = run;
        g_cursor[j]   = run;
        g_dinv[j]     = rsqrtf((float)d + 1.0f);
    }
    if (j == 0) g_rowstart[NUM_PROTEINS] = E_SG;
}

// ---------------- CSR fill (src only) ----------------
__global__ void k_fill(const int* __restrict__ ei) {
    int e = blockIdx.x * blockDim.x + threadIdx.x;
    if (e >= E_SG) return;
    int s = ei[e];
    int d = ei[E_SG + e];
    int pos = atomicAdd(&g_cursor[d], 1);
    g_esrc[pos] = s;
}

// ---------------- WMMA fp16 GEMM: C[M,256](fp16) = A[M,256] @ B[256,256] ----------------
template<int AHALF>
__global__ void k_gemm_w(const void* __restrict__ Ap, const __half* __restrict__ B,
                         __half* __restrict__ C, int M) {
    __shared__ __align__(16) __half As[128][40];
    __shared__ __align__(16) __half Bs[32][72];
    __shared__ __align__(16) float  Cs[128][64];
    int bm = blockIdx.x * 128, bn = blockIdx.y * 64;
    int tid = threadIdx.x;
    int warp = tid >> 5;
    int wm = warp & 3, wn = warp >> 2;
    wmma::fragment<wmma::accumulator, 16, 16, 16, float> c[2][2];
#pragma unroll
    for (int i = 0; i < 2; ++i)
#pragma unroll
        for (int j = 0; j < 2; ++j) wmma::fill_fragment(c[i][j], 0.f);

    for (int k0 = 0; k0 < 256; k0 += 32) {
        if (AHALF) {
            const __half* A = (const __half*)Ap;
#pragma unroll
            for (int l = 0; l < 2; ++l) {
                int idx = tid + l * 256;
                int r = idx >> 2, seg = (idx & 3) * 8;
                uint4 v = make_uint4(0, 0, 0, 0);
                int gr = bm + r;
                if (gr < M) v = *(const uint4*)(A + (size_t)gr * 256 + k0 + seg);
                *(uint4*)&As[r][seg] = v;
            }
        } else {
            const float* A = (const float*)Ap;
#pragma unroll
            for (int l = 0; l < 4; ++l) {
                int idx = tid + l * 256;
                int r = idx >> 3, c4 = (idx & 7) * 4;
                float4 v = make_float4(0.f, 0.f, 0.f, 0.f);
                int gr = bm + r;
                if (gr < M) v = *(const float4*)(A + (size_t)gr * 256 + k0 + c4);
                *(__half2*)&As[r][c4]     = __floats2half2_rn(v.x, v.y);
                *(__half2*)&As[r][c4 + 2] = __floats2half2_rn(v.z, v.w);
            }
        }
        {
            int r = tid >> 3, seg = (tid & 7) * 8;
            uint4 v = *(const uint4*)(B + (size_t)(k0 + r) * 256 + bn + seg);
            *(uint4*)&Bs[r][seg] = v;
        }
        __syncthreads();
#pragma unroll
        for (int kk = 0; kk < 32; kk += 16) {
            wmma::fragment<wmma::matrix_a, 16, 16, 16, __half, wmma::row_major> a0, a1;
            wmma::fragment<wmma::matrix_b, 16, 16, 16, __half, wmma::row_major> b0, b1;
            wmma::load_matrix_sync(a0, &As[wm * 32][kk], 40);
            wmma::load_matrix_sync(a1, &As[wm * 32 + 16][kk], 40);
            wmma::load_matrix_sync(b0, &Bs[kk][wn * 32], 72);
            wmma::load_matrix_sync(b1, &Bs[kk][wn * 32 + 16], 72);
            wmma::mma_sync(c[0][0], a0, b0, c[0][0]);
            wmma::mma_sync(c[0][1], a0, b1, c[0][1]);
            wmma::mma_sync(c[1][0], a1, b0, c[1][0]);
            wmma::mma_sync(c[1][1], a1, b1, c[1][1]);
        }
        __syncthreads();
    }
    // stage fp32 accumulators -> smem -> fp16 global
#pragma unroll
    for (int i = 0; i < 2; ++i)
#pragma unroll
        for (int j = 0; j < 2; ++j)
            wmma::store_matrix_sync(&Cs[wm * 32 + i * 16][wn * 32 + j * 16], c[i][j], 64,
                                    wmma::mem_row_major);
    __syncthreads();
#pragma unroll
    for (int l = 0; l < 4; ++l) {
        int idx = tid + l * 256;
        int r = idx >> 3, seg = (idx & 7) * 8;
        int gr = bm + r;
        if (gr < M) {
            float4 v0 = *(const float4*)&Cs[r][seg];
            float4 v1 = *(const float4*)&Cs[r][seg + 4];
            uint4 ov; __half2* oh = (__half2*)&ov;
            oh[0] = __floats2half2_rn(v0.x, v0.y);
            oh[1] = __floats2half2_rn(v0.z, v0.w);
            oh[2] = __floats2half2_rn(v1.x, v1.y);
            oh[3] = __floats2half2_rn(v1.z, v1.w);
            *(uint4*)(C + (size_t)gr * 256 + bn + seg) = ov;
        }
    }
}

// ---------------- warp-per-row CSR aggregation, fp16 gather, fp32 accum ----------------
// out = dinv_d * ( sum_e dinv[src_e]*hw[src_e]  +  dinv_d*hw[row] ) + bias (+resid) (relu)
__global__ void k_agg(const __half* __restrict__ hw, const float* __restrict__ bias,
                      const __half* __restrict__ resid, __half* __restrict__ outp,
                      int do_relu) {
    int warp = (blockIdx.x * blockDim.x + threadIdx.x) >> 5;
    if (warp >= NUM_PROTEINS) return;
    int lane = threadIdx.x & 31;
    float acc[8];
#pragma unroll
    for (int i = 0; i < 8; ++i) acc[i] = 0.f;
    int beg = g_rowstart[warp], end = g_rowstart[warp + 1];
    float dinv_d = g_dinv[warp];

    for (int base = beg; base < end; base += 32) {
        int idx = base + lane;
        int   sreg = 0;
        float wreg = 0.f;
        if (idx < end) { sreg = g_esrc[idx]; wreg = g_dinv[sreg]; }
        int n = end - base; if (n > 32) n = 32;
        for (int j = 0; j < n; ++j) {
            int   sj = __shfl_sync(0xffffffffu, sreg, j);
            float wj = __shfl_sync(0xffffffffu, wreg, j);
            uint4 vv = *(const uint4*)(hw + (size_t)sj * EMBED + lane * 8);
            __half2* h = (__half2*)&vv;
#pragma unroll
            for (int q = 0; q < 4; ++q) {
                float2 f = __half22float2(h[q]);
                acc[2 * q]     = fmaf(wj, f.x, acc[2 * q]);
                acc[2 * q + 1] = fmaf(wj, f.y, acc[2 * q + 1]);
            }
        }
    }

    uint4 sv = *(const uint4*)(hw + (size_t)warp * EMBED + lane * 8);
    __half2* sh = (__half2*)&sv;
    float4 b0 = *(const float4*)(bias + lane * 8);
    float4 b1 = *(const float4*)(bias + lane * 8 + 4);
    float bb[8] = {b0.x, b0.y, b0.z, b0.w, b1.x, b1.y, b1.z, b1.w};
#pragma unroll
    for (int q = 0; q < 4; ++q) {
        float2 f = __half22float2(sh[q]);
        acc[2 * q]     = (acc[2 * q]     + dinv_d * f.x) * dinv_d + bb[2 * q];
        acc[2 * q + 1] = (acc[2 * q + 1] + dinv_d * f.y) * dinv_d + bb[2 * q + 1];
    }
    if (resid) {
        uint4 rv = *(const uint4*)(resid + (size_t)warp * EMBED + lane * 8);
        __half2* rh = (__half2*)&rv;
#pragma unroll
        for (int q = 0; q < 4; ++q) {
            float2 f = __half22float2(rh[q]);
            acc[2 * q] += f.x; acc[2 * q + 1] += f.y;
        }
    }
    if (do_relu) {
#pragma unroll
        for (int i = 0; i < 8; ++i) acc[i] = fmaxf(acc[i], 0.f);
    }
    uint4 ov; __half2* oh = (__half2*)&ov;
#pragma unroll
    for (int q = 0; q < 4; ++q) oh[q] = __floats2half2_rn(acc[2 * q], acc[2 * q + 1]);
    *(uint4*)(outp + (size_t)warp * EMBED + lane * 8) = ov;
}

// ---------------- drug segment boundaries from sorted sga ----------------
__global__ void k_dseg(const int* __restrict__ didx) {
    int i = blockIdx.x * blockDim.x + threadIdx.x;
    if (i >= N_SG) return;
    int cur  = didx[i];
    int prev = (i == 0) ? -1 : didx[i - 1];
    for (int t = prev + 1; t <= cur; ++t) g_dstart[t] = i;
    if (i == N_SG - 1)
        for (int t = cur + 1; t <= NUM_DRUGS; ++t) g_dstart[t] = N_SG;
}

// ---------------- block-per-drug pooling (no atomics), normalized output ----------------
__global__ void k_pool(const int* __restrict__ nodes, const __half* __restrict__ h2) {
    int d = blockIdx.x;
    int c = threadIdx.x;                  // channel
    int s = g_dstart[d], e = g_dstart[d + 1];
    float acc = 0.f;
    int n = s;
    for (; n + 4 <= e; n += 4) {
        int i0 = nodes[n], i1 = nodes[n + 1], i2 = nodes[n + 2], i3 = nodes[n + 3];
        float v0 = __half2float(h2[(size_t)i0 * EMBED + c]);
        float v1 = __half2float(h2[(size_t)i1 * EMBED + c]);
        float v2 = __half2float(h2[(size_t)i2 * EMBED + c]);
        float v3 = __half2float(h2[(size_t)i3 * EMBED + c]);
        acc += (v0 + v1) + (v2 + v3);
    }
    for (; n < e; ++n)
        acc += __half2float(h2[(size_t)nodes[n] * EMBED + c]);
    int cnt = e - s; if (cnt < 1) cnt = 1;
    g_demb[(size_t)d * EMBED + c] = acc * (1.0f / (float)cnt);
}

// ---------------- head: warp-per-pair dot products on normalized embeddings ----------------
__global__ void k_head(const int* __restrict__ ddb, float* __restrict__ out) {
    int warp = (blockIdx.x * blockDim.x + threadIdx.x) >> 5;
    if (warp >= B_DD) return;
    int lane = threadIdx.x & 31;
    int a = ddb[warp];
    int b = ddb[B_DD + warp];
    const float4* pa = (const float4*)(g_demb + (size_t)a * EMBED + lane * 8);
    const float4* pb = (const float4*)(g_demb + (size_t)b * EMBED + lane * 8);
    float4 a0 = pa[0], a1 = pa[1];
    float4 b0 = pb[0], b1 = pb[1];
    float dot = a0.x * b0.x + a0.y * b0.y + a0.z * b0.z + a0.w * b0.w
              + a1.x * b1.x + a1.y * b1.y + a1.z * b1.z + a1.w * b1.w;
#pragma unroll
    for (int off = 16; off > 0; off >>= 1)
        dot += __shfl_down_sync(0xffffffffu, dot, off);
    if (lane == 0) out[warp] = dot;
}

// ---------------- launch ----------------
extern "C" void kernel_launch(void* const* d_in, const int* in_sizes, int n_in,
                              void* d_out, int out_size) {
    const float* x   = (const float*)d_in[0];
    const int*   ddb = (const int*)  d_in[1];
    const int*   ei  = (const int*)  d_in[4];
    const int*   sgn = (const int*)  d_in[5];
    const int*   sga = (const int*)  d_in[6];
    const float* W1  = (const float*)d_in[7];
    const float* b1  = (const float*)d_in[8];
    const float* W2  = (const float*)d_in[9];
    const float* b2  = (const float*)d_in[10];
    float* out = (float*)d_out;

    __half *hwh, *h1h, *h2h, *W1h, *W2h;
    cudaGetSymbolAddress((void**)&hwh, g_hwh4);
    cudaGetSymbolAddress((void**)&h1h, g_h1h4);
    cudaGetSymbolAddress((void**)&h2h, g_h2h4);
    cudaGetSymbolAddress((void**)&W1h, g_W1h4);
    cudaGetSymbolAddress((void**)&W2h, g_W2h4);

    k_prep0<<<128, 256>>>(W1, W2, W1h, W2h);
    k_count<<<(E_SG + 255) / 256, 256>>>(ei);
    k_bsum<<<NBLK, 128>>>();
    k_bscan<<<1, 192>>>();
    k_write<<<NBLK, 128>>>();
    k_fill<<<(E_SG + 255) / 256, 256>>>(ei);

    dim3 ggrid(NBLK, 256 / 64);
    // Layer 1
    k_gemm_w<0><<<ggrid, 256>>>((const void*)x, W1h, hwh, NUM_PROTEINS);
    k_agg<<<(NUM_PROTEINS * 32 + 255) / 256, 256>>>(hwh, b1, (const __half*)nullptr, h1h, 1);
    // Layer 2 (residual, no relu)
    k_gemm_w<1><<<ggrid, 256>>>((const void*)h1h, W2h, hwh, NUM_PROTEINS);
    k_agg<<<(NUM_PROTEINS * 32 + 255) / 256, 256>>>(hwh, b2, h1h, h2h, 0);

    k_dseg<<<(N_SG + 255) / 256, 256>>>(sga);
    k_pool<<<NUM_DRUGS, 256>>>(sgn, h2h);
    k_head<<<(B_DD * 32 + 255) / 256, 256>>>(ddb, out);
}

// round 5
// speedup vs baseline: 1.9098x; 1.1471x over previous
#include <cuda_runtime.h>
#include <cuda_fp16.h>
#include <mma.h>
#include <cstdint>
using namespace nvcuda;

#define NUM_PROTEINS 19000
#define NUM_DRUGS    1024
#define EMBED        256
#define E_SG         1500000
#define N_SG         800000
#define B_DD         4096
#define NBLK         149            // ceil(19000/128)

// ---------------- scratch (device globals; no allocation) ----------------
__device__ uint4 g_hwh4[NUM_PROTEINS * EMBED / 8];      // GEMM out fp16
__device__ uint4 g_h1h4[NUM_PROTEINS * EMBED / 8];      // h1 fp16
__device__ uint4 g_h2h4[NUM_PROTEINS * EMBED / 8];      // h2 fp16
__device__ uint2 g_q8v [NUM_PROTEINS * EMBED / 8];      // hw quantized int8
__device__ float g_qd  [NUM_PROTEINS];                  // dinv[row]*qscale[row]
__device__ uint4 g_W1h4[EMBED * EMBED / 8];
__device__ uint4 g_W2h4[EMBED * EMBED / 8];
__device__ int   g_degi[NUM_PROTEINS];
__device__ float g_dinv[NUM_PROTEINS];
__device__ int   g_rowstart[NUM_PROTEINS + 1];
__device__ int   g_cursor[NUM_PROTEINS];
__device__ int   g_esrc[E_SG];
__device__ int   g_bsum[NBLK];
__device__ int   g_boff[NBLK];
__device__ int   g_dstart[NUM_DRUGS + 1];
__device__ float g_demb[NUM_DRUGS * EMBED];

// safe sign-extended byte k of v (arithmetic shifts only)
__device__ __forceinline__ int sx8s(unsigned v, int k) {
    return ((int)(v << ((3 - k) * 8))) >> 24;
}

// ---------------- prep0: convert W1/W2 to fp16, zero degree counters ----------------
__global__ void k_prep0(const float* __restrict__ W1, const float* __restrict__ W2,
                        __half* __restrict__ W1h, __half* __restrict__ W2h) {
    int i = blockIdx.x * blockDim.x + threadIdx.x;
    const int n4 = EMBED * EMBED / 4;
    if (i < n4) {
        float4 v = ((const float4*)W1)[i];
        ((__half2*)W1h)[2 * i]     = __floats2half2_rn(v.x, v.y);
        ((__half2*)W1h)[2 * i + 1] = __floats2half2_rn(v.z, v.w);
    } else {
        int j = i - n4;
        float4 v = ((const float4*)W2)[j];
        ((__half2*)W2h)[2 * j]     = __floats2half2_rn(v.x, v.y);
        ((__half2*)W2h)[2 * j + 1] = __floats2half2_rn(v.z, v.w);
    }
    if (i < NUM_PROTEINS) g_degi[i] = 0;
}

// ---------------- degree count ----------------
__global__ void k_count(const int* __restrict__ ei) {
    int e = blockIdx.x * blockDim.x + threadIdx.x;
    if (e >= E_SG) return;
    atomicAdd(&g_degi[ei[E_SG + e]], 1);
}

// ---------------- scan phase 1 ----------------
__global__ void k_bsum() {
    __shared__ int ws[4];
    int j = blockIdx.x * 128 + threadIdx.x;
    int v = (j < NUM_PROTEINS) ? g_degi[j] : 0;
#pragma unroll
    for (int off = 16; off > 0; off >>= 1) v += __shfl_down_sync(0xffffffffu, v, off);
    int lane = threadIdx.x & 31, w = threadIdx.x >> 5;
    if (lane == 0) ws[w] = v;
    __syncthreads();
    if (threadIdx.x == 0) g_bsum[blockIdx.x] = ws[0] + ws[1] + ws[2] + ws[3];
}

// ---------------- scan phase 2 ----------------
__global__ void k_bscan() {
    __shared__ int wsum[6];
    int t = threadIdx.x;
    int lane = t & 31, w = t >> 5;
    int s = (t < NBLK) ? g_bsum[t] : 0;
    int v = s;
#pragma unroll
    for (int off = 1; off < 32; off <<= 1) {
        int u = __shfl_up_sync(0xffffffffu, v, off);
        if (lane >= off) v += u;
    }
    if (lane == 31) wsum[w] = v;
    __syncthreads();
    if (w == 0 && lane < 6) {
        int x = wsum[lane];
#pragma unroll
        for (int off = 1; off < 6; off <<= 1) {
            int u = __shfl_up_sync(0x3fu, x, off);
            if (lane >= off) x += u;
        }
        wsum[lane] = x;
    }
    __syncthreads();
    int excl = v - s + (w ? wsum[w - 1] : 0);
    if (t < NBLK) g_boff[t] = excl;
}

// ---------------- scan phase 3 ----------------
__global__ void k_write() {
    __shared__ int wsum[4];
    int t = threadIdx.x;
    int j = blockIdx.x * 128 + t;
    int d = (j < NUM_PROTEINS) ? g_degi[j] : 0;
    int lane = t & 31, w = t >> 5;
    int v = d;
#pragma unroll
    for (int off = 1; off < 32; off <<= 1) {
        int u = __shfl_up_sync(0xffffffffu, v, off);
        if (lane >= off) v += u;
    }
    if (lane == 31) wsum[w] = v;
    __syncthreads();
    if (w == 0 && lane < 4) {
        int x = wsum[lane];
#pragma unroll
        for (int off = 1; off < 4; off <<= 1) {
            int u = __shfl_up_sync(0xfu, x, off);
            if (lane >= off) x += u;
        }
        wsum[lane] = x;
    }
    __syncthreads();
    int run = g_boff[blockIdx.x] + v - d + (w ? wsum[w - 1] : 0);
    if (j < NUM_PROTEINS) {
        g_rowstart[j] = run;
        g_cursor[j]   = run;
        g_dinv[j]     = rsqrtf((float)d + 1.0f);
    }
    if (j == 0) g_rowstart[NUM_PROTEINS] = E_SG;
}

// ---------------- CSR fill ----------------
__global__ void k_fill(const int* __restrict__ ei) {
    int e = blockIdx.x * blockDim.x + threadIdx.x;
    if (e >= E_SG) return;
    int s = ei[e];
    int d = ei[E_SG + e];
    int pos = atomicAdd(&g_cursor[d], 1);
    g_esrc[pos] = s;
}

// ---------------- WMMA fp16 GEMM ----------------
template<int AHALF>
__global__ void k_gemm_w(const void* __restrict__ Ap, const __half* __restrict__ B,
                         __half* __restrict__ C, int M) {
    __shared__ __align__(16) __half As[128][40];
    __shared__ __align__(16) __half Bs[32][72];
    __shared__ __align__(16) float  Cs[128][64];
    int bm = blockIdx.x * 128, bn = blockIdx.y * 64;
    int tid = threadIdx.x;
    int warp = tid >> 5;
    int wm = warp & 3, wn = warp >> 2;
    wmma::fragment<wmma::accumulator, 16, 16, 16, float> c[2][2];
#pragma unroll
    for (int i = 0; i < 2; ++i)
#pragma unroll
        for (int j = 0; j < 2; ++j) wmma::fill_fragment(c[i][j], 0.f);

    for (int k0 = 0; k0 < 256; k0 += 32) {
        if (AHALF) {
            const __half* A = (const __half*)Ap;
#pragma unroll
            for (int l = 0; l < 2; ++l) {
                int idx = tid + l * 256;
                int r = idx >> 2, seg = (idx & 3) * 8;
                uint4 v = make_uint4(0, 0, 0, 0);
                int gr = bm + r;
                if (gr < M) v = *(const uint4*)(A + (size_t)gr * 256 + k0 + seg);
                *(uint4*)&As[r][seg] = v;
            }
        } else {
            const float* A = (const float*)Ap;
#pragma unroll
            for (int l = 0; l < 4; ++l) {
                int idx = tid + l * 256;
                int r = idx >> 3, c4 = (idx & 7) * 4;
                float4 v = make_float4(0.f, 0.f, 0.f, 0.f);
                int gr = bm + r;
                if (gr < M) v = *(const float4*)(A + (size_t)gr * 256 + k0 + c4);
                *(__half2*)&As[r][c4]     = __floats2half2_rn(v.x, v.y);
                *(__half2*)&As[r][c4 + 2] = __floats2half2_rn(v.z, v.w);
            }
        }
        {
            int r = tid >> 3, seg = (tid & 7) * 8;
            uint4 v = *(const uint4*)(B + (size_t)(k0 + r) * 256 + bn + seg);
            *(uint4*)&Bs[r][seg] = v;
        }
        __syncthreads();
#pragma unroll
        for (int kk = 0; kk < 32; kk += 16) {
            wmma::fragment<wmma::matrix_a, 16, 16, 16, __half, wmma::row_major> a0, a1;
            wmma::fragment<wmma::matrix_b, 16, 16, 16, __half, wmma::row_major> b0, b1;
            wmma::load_matrix_sync(a0, &As[wm * 32][kk], 40);
            wmma::load_matrix_sync(a1, &As[wm * 32 + 16][kk], 40);
            wmma::load_matrix_sync(b0, &Bs[kk][wn * 32], 72);
            wmma::load_matrix_sync(b1, &Bs[kk][wn * 32 + 16], 72);
            wmma::mma_sync(c[0][0], a0, b0, c[0][0]);
            wmma::mma_sync(c[0][1], a0, b1, c[0][1]);
            wmma::mma_sync(c[1][0], a1, b0, c[1][0]);
            wmma::mma_sync(c[1][1], a1, b1, c[1][1]);
        }
        __syncthreads();
    }
#pragma unroll
    for (int i = 0; i < 2; ++i)
#pragma unroll
        for (int j = 0; j < 2; ++j)
            wmma::store_matrix_sync(&Cs[wm * 32 + i * 16][wn * 32 + j * 16], c[i][j], 64,
                                    wmma::mem_row_major);
    __syncthreads();
#pragma unroll
    for (int l = 0; l < 4; ++l) {
        int idx = tid + l * 256;
        int r = idx >> 3, seg = (idx & 7) * 8;
        int gr = bm + r;
        if (gr < M) {
            float4 v0 = *(const float4*)&Cs[r][seg];
            float4 v1 = *(const float4*)&Cs[r][seg + 4];
            uint4 ov; __half2* oh = (__half2*)&ov;
            oh[0] = __floats2half2_rn(v0.x, v0.y);
            oh[1] = __floats2half2_rn(v0.z, v0.w);
            oh[2] = __floats2half2_rn(v1.x, v1.y);
            oh[3] = __floats2half2_rn(v1.z, v1.w);
            *(uint4*)(C + (size_t)gr * 256 + bn + seg) = ov;
        }
    }
}

// ---------------- quantize hw rows to int8 (warp per row) ----------------
__global__ void k_quant(const __half* __restrict__ hw) {
    int row = blockIdx.x * 8 + (threadIdx.x >> 5);
    if (row >= NUM_PROTEINS) return;
    int lane = threadIdx.x & 31;
    uint4 v = *(const uint4*)(hw + (size_t)row * EMBED + lane * 8);
    __half2* h = (__half2*)&v;
    float f[8];
#pragma unroll
    for (int q = 0; q < 4; ++q) {
        float2 p = __half22float2(h[q]);
        f[2 * q] = p.x; f[2 * q + 1] = p.y;
    }
    float m = 0.f;
#pragma unroll
    for (int i = 0; i < 8; ++i) m = fmaxf(m, fabsf(f[i]));
#pragma unroll
    for (int off = 16; off > 0; off >>= 1)
        m = fmaxf(m, __shfl_xor_sync(0xffffffffu, m, off));
    float inv = (m > 1e-30f) ? 127.f / m : 0.f;
    int b[8];
#pragma unroll
    for (int i = 0; i < 8; ++i) {
        float q = fminf(fmaxf(f[i] * inv, -127.f), 127.f);
        b[i] = __float2int_rn(q);
    }
    uint2 o;
    o.x = (unsigned)(b[0] & 255) | ((unsigned)(b[1] & 255) << 8) |
          ((unsigned)(b[2] & 255) << 16) | ((unsigned)(b[3] & 255) << 24);
    o.y = (unsigned)(b[4] & 255) | ((unsigned)(b[5] & 255) << 8) |
          ((unsigned)(b[6] & 255) << 16) | ((unsigned)(b[7] & 255) << 24);
    g_q8v[(size_t)row * 32 + lane] = o;
    if (lane == 0) g_qd[row] = (m * (1.f / 127.f)) * g_dinv[row];
}

// ---------------- CSR aggregation: int8 edge gather, fp16 self/resid, fp16 out ----------------
template<int LAYER>
__global__ void k_agg8(const __half* __restrict__ hw, const float* __restrict__ bias,
                       const __half* __restrict__ resid, __half* __restrict__ outp) {
    int row = (blockIdx.x * blockDim.x + threadIdx.x) >> 5;
    if (row >= NUM_PROTEINS) return;
    int lane = threadIdx.x & 31;
    const int8_t* q8 = (const int8_t*)g_q8v;
    float acc[8];
#pragma unroll
    for (int i = 0; i < 8; ++i) acc[i] = 0.f;
    int beg = g_rowstart[row], end = g_rowstart[row + 1];
    float dinv_d = g_dinv[row];

    for (int base = beg; base < end; base += 32) {
        int idx = base + lane;
        int   sreg = 0;
        float wreg = 0.f;
        if (idx < end) { sreg = g_esrc[idx]; wreg = g_qd[sreg]; }
        int n = end - base; if (n > 32) n = 32;
        for (int j = 0; j < n; ++j) {
            int   sj = __shfl_sync(0xffffffffu, sreg, j);
            float wj = __shfl_sync(0xffffffffu, wreg, j);
            uint2 w = *(const uint2*)(q8 + (size_t)sj * EMBED + lane * 8);
            acc[0] = fmaf(wj, (float)sx8s(w.x, 0), acc[0]);
            acc[1] = fmaf(wj, (float)sx8s(w.x, 1), acc[1]);
            acc[2] = fmaf(wj, (float)sx8s(w.x, 2), acc[2]);
            acc[3] = fmaf(wj, (float)sx8s(w.x, 3), acc[3]);
            acc[4] = fmaf(wj, (float)sx8s(w.y, 0), acc[4]);
            acc[5] = fmaf(wj, (float)sx8s(w.y, 1), acc[5]);
            acc[6] = fmaf(wj, (float)sx8s(w.y, 2), acc[6]);
            acc[7] = fmaf(wj, (float)sx8s(w.y, 3), acc[7]);
        }
    }

    // self term from fp16 hw (exact path), bias, epilogue
    uint4 sv = *(const uint4*)(hw + (size_t)row * EMBED + lane * 8);
    __half2* sh = (__half2*)&sv;
    float4 b0 = *(const float4*)(bias + lane * 8);
    float4 b1 = *(const float4*)(bias + lane * 8 + 4);
    float bb[8] = {b0.x, b0.y, b0.z, b0.w, b1.x, b1.y, b1.z, b1.w};
#pragma unroll
    for (int q = 0; q < 4; ++q) {
        float2 f = __half22float2(sh[q]);
        acc[2 * q]     = (acc[2 * q]     + dinv_d * f.x) * dinv_d + bb[2 * q];
        acc[2 * q + 1] = (acc[2 * q + 1] + dinv_d * f.y) * dinv_d + bb[2 * q + 1];
    }
    if (LAYER == 1) {
#pragma unroll
        for (int i = 0; i < 8; ++i) acc[i] = fmaxf(acc[i], 0.f);
    } else {
        uint4 rv = *(const uint4*)(resid + (size_t)row * EMBED + lane * 8);
        __half2* rh = (__half2*)&rv;
#pragma unroll
        for (int q = 0; q < 4; ++q) {
            float2 f = __half22float2(rh[q]);
            acc[2 * q] += f.x; acc[2 * q + 1] += f.y;
        }
    }
    uint4 ov; __half2* oh = (__half2*)&ov;
#pragma unroll
    for (int q = 0; q < 4; ++q) oh[q] = __floats2half2_rn(acc[2 * q], acc[2 * q + 1]);
    *(uint4*)(outp + (size_t)row * EMBED + lane * 8) = ov;
}

// ---------------- drug segment boundaries ----------------
__global__ void k_dseg(const int* __restrict__ didx) {
    int i = blockIdx.x * blockDim.x + threadIdx.x;
    if (i >= N_SG) return;
    int cur  = didx[i];
    int prev = (i == 0) ? -1 : didx[i - 1];
    for (int t = prev + 1; t <= cur; ++t) g_dstart[t] = i;
    if (i == N_SG - 1)
        for (int t = cur + 1; t <= NUM_DRUGS; ++t) g_dstart[t] = N_SG;
}

// ---------------- fp16 pooling: 8 warps per drug ----------------
__global__ void k_poolh(const int* __restrict__ nodes, const __half* __restrict__ h2) {
    __shared__ float sm[8][256];
    int d = blockIdx.x;
    int lane = threadIdx.x & 31, w = threadIdx.x >> 5;
    int s = g_dstart[d], e = g_dstart[d + 1];
    float acc[8];
#pragma unroll
    for (int i = 0; i < 8; ++i) acc[i] = 0.f;
    for (int n = s + w; n < e; n += 8) {
        int node = __ldg(nodes + n);
        uint4 v = *(const uint4*)(h2 + (size_t)node * EMBED + lane * 8);
        __half2* h = (__half2*)&v;
#pragma unroll
        for (int q = 0; q < 4; ++q) {
            float2 f = __half22float2(h[q]);
            acc[2 * q] += f.x; acc[2 * q + 1] += f.y;
        }
    }
#pragma unroll
    for (int i = 0; i < 8; ++i) sm[w][lane * 8 + i] = acc[i];
    __syncthreads();
    int c = threadIdx.x;
    float t = sm[0][c] + sm[1][c] + sm[2][c] + sm[3][c]
            + sm[4][c] + sm[5][c] + sm[6][c] + sm[7][c];
    int cnt = e - s; if (cnt < 1) cnt = 1;
    g_demb[(size_t)d * EMBED + c] = t * (1.0f / (float)cnt);
}

// ---------------- head ----------------
__global__ void k_head(const int* __restrict__ ddb, float* __restrict__ out) {
    int warp = (blockIdx.x * blockDim.x + threadIdx.x) >> 5;
    if (warp >= B_DD) return;
    int lane = threadIdx.x & 31;
    int a = ddb[warp];
    int b = ddb[B_DD + warp];
    const float4* pa = (const float4*)(g_demb + (size_t)a * EMBED + lane * 8);
    const float4* pb = (const float4*)(g_demb + (size_t)b * EMBED + lane * 8);
    float4 a0 = pa[0], a1 = pa[1];
    float4 b0 = pb[0], b1 = pb[1];
    float dot = a0.x * b0.x + a0.y * b0.y + a0.z * b0.z + a0.w * b0.w
              + a1.x * b1.x + a1.y * b1.y + a1.z * b1.z + a1.w * b1.w;
#pragma unroll
    for (int off = 16; off > 0; off >>= 1)
        dot += __shfl_down_sync(0xffffffffu, dot, off);
    if (lane == 0) out[warp] = dot;
}

// ---------------- launch ----------------
extern "C" void kernel_launch(void* const* d_in, const int* in_sizes, int n_in,
                              void* d_out, int out_size) {
    const float* x   = (const float*)d_in[0];
    const int*   ddb = (const int*)  d_in[1];
    const int*   ei  = (const int*)  d_in[4];
    const int*   sgn = (const int*)  d_in[5];
    const int*   sga = (const int*)  d_in[6];
    const float* W1  = (const float*)d_in[7];
    const float* b1  = (const float*)d_in[8];
    const float* W2  = (const float*)d_in[9];
    const float* b2  = (const float*)d_in[10];
    float* out = (float*)d_out;

    __half *hwh, *h1h, *h2h, *W1h, *W2h;
    cudaGetSymbolAddress((void**)&hwh, g_hwh4);
    cudaGetSymbolAddress((void**)&h1h, g_h1h4);
    cudaGetSymbolAddress((void**)&h2h, g_h2h4);
    cudaGetSymbolAddress((void**)&W1h, g_W1h4);
    cudaGetSymbolAddress((void**)&W2h, g_W2h4);

    k_prep0<<<128, 256>>>(W1, W2, W1h, W2h);
    k_count<<<(E_SG + 255) / 256, 256>>>(ei);
    k_bsum<<<NBLK, 128>>>();
    k_bscan<<<1, 192>>>();
    k_write<<<NBLK, 128>>>();
    k_fill<<<(E_SG + 255) / 256, 256>>>(ei);

    dim3 ggrid(NBLK, 256 / 64);
    // Layer 1
    k_gemm_w<0><<<ggrid, 256>>>((const void*)x, W1h, hwh, NUM_PROTEINS);
    k_quant<<<(NUM_PROTEINS + 7) / 8, 256>>>(hwh);
    k_agg8<1><<<(NUM_PROTEINS * 32 + 255) / 256, 256>>>(hwh, b1, (const __half*)nullptr, h1h);
    // Layer 2 (residual, no relu)
    k_gemm_w<1><<<ggrid, 256>>>((const void*)h1h, W2h, hwh, NUM_PROTEINS);
    k_quant<<<(NUM_PROTEINS + 7) / 8, 256>>>(hwh);
    k_agg8<2><<<(NUM_PROTEINS * 32 + 255) / 256, 256>>>(hwh, b2, h1h, h2h);

    k_dseg<<<(N_SG + 255) / 256, 256>>>(sga);
    k_poolh<<<NUM_DRUGS, 256>>>(sgn, h2h);
    k_head<<<(B_DD * 32 + 255) / 256, 256>>>(ddb, out);
}